// round 8
// baseline (speedup 1.0000x reference)
#include <cuda_runtime.h>
#include <cuda_bf16.h>

#define NC 4
#define D  256

__device__ float        g_sum[NC * D];   // zero-initialized at load; self-cleaned per run
__device__ unsigned int g_cnt[NC];
__device__ unsigned int g_done;

// Two packed 1.0f floats for the f32x2 mask.
#define ONE2 0x3F8000003F800000ULL
// Packed dual-FMA (Blackwell f32x2): acc += v * m (2 lanes at once)
#define FMA2(acc, v, m) \
    asm("fma.rn.f32x2 %0, %1, %2, %0;" : "+l"(acc) : "l"(v), "l"(m))

#define ACC_ROW(v, lbl)                                                   \
    do {                                                                  \
        const unsigned long long _m0 = ((lbl) == 0) ? ONE2 : 0ULL;        \
        const unsigned long long _m1 = ((lbl) == 1) ? ONE2 : 0ULL;        \
        const unsigned long long _m2 = ((lbl) == 2) ? ONE2 : 0ULL;        \
        const unsigned long long _m3 = ((lbl) == 3) ? ONE2 : 0ULL;        \
        FMA2(a00, (v).x, _m0); FMA2(a01, (v).y, _m0);                     \
        FMA2(a10, (v).x, _m1); FMA2(a11, (v).y, _m1);                     \
        FMA2(a20, (v).x, _m2); FMA2(a21, (v).y, _m2);                     \
        FMA2(a30, (v).x, _m3); FMA2(a31, (v).y, _m3);                     \
    } while (0)

// 256 threads/CTA = 4 groups of 64 (2 warps). Unit = 32 contiguous rows per
// group. Labels staged in a warp register (lane j = label of row j), broadcast
// per row via shfl. NO barriers in the mainloop -> loads stream continuously.
__global__ __launch_bounds__(256, 4) void accum_kernel(
    const ulonglong2* __restrict__ feat,   // [nrows*64] 16B chunks
    const int*        __restrict__ labels, // [nrows]
    int nrows,
    float* __restrict__ out, int out_size)
{
    const int tid  = threadIdx.x;
    const int grp  = tid >> 6;
    const int lane = tid & 63;   // float4 column within the row
    const int l32  = tid & 31;

    unsigned long long a00 = 0, a01 = 0, a10 = 0, a11 = 0;
    unsigned long long a20 = 0, a21 = 0, a30 = 0, a31 = 0;
    int c0 = 0, c1 = 0, c2 = 0, c3 = 0;

    const int nunits  = (nrows + 31) >> 5;
    const int ustride = gridDim.x * 4;

    for (int u = blockIdx.x * 4 + grp; u < nunits; u += ustride) {
        const int rbase = u << 5;

        // Stage this unit's 32 labels into a register (coalesced 128B load).
        const int idx = rbase + l32;
        const int myl = (idx < nrows) ? __ldcs(labels + idx) : -1;

        // Count each label once: only warp0 of each group counts.
        if ((tid & 32) == 0) {
            c0 += (myl == 0); c1 += (myl == 1);
            c2 += (myl == 2); c3 += (myl == 3);
        }

        const size_t fbase = (size_t)rbase * 64 + lane;
        const int lim = nrows - rbase;

        if (lim >= 32) {
            #pragma unroll
            for (int j0 = 0; j0 < 32; j0 += 8) {
                ulonglong2 v[8];
                #pragma unroll
                for (int k = 0; k < 8; k++)
                    v[k] = __ldcs(&feat[fbase + (size_t)(j0 + k) * 64]);
                #pragma unroll
                for (int k = 0; k < 8; k++) {
                    const int lbl = __shfl_sync(0xffffffffu, myl, j0 + k);
                    ACC_ROW(v[k], lbl);
                }
            }
        } else {
            for (int j = 0; j < lim; j++) {
                const int lbl = __shfl_sync(0xffffffffu, myl, j);
                const ulonglong2 v = __ldcs(&feat[fbase + (size_t)j * 64]);
                ACC_ROW(v, lbl);
            }
        }
    }

    // ---- Block reduction into global scratch ----
    __shared__ unsigned long long s[NC][4][128];   // float[NC][4][256] view, 16 KB
    __shared__ unsigned int scnt[NC];

    if (tid < NC) scnt[tid] = 0u;

    const int p = lane * 2;
    s[0][grp][p] = a00; s[0][grp][p + 1] = a01;
    s[1][grp][p] = a10; s[1][grp][p + 1] = a11;
    s[2][grp][p] = a20; s[2][grp][p + 1] = a21;
    s[3][grp][p] = a30; s[3][grp][p + 1] = a31;

    // Warp-level count reduce (non-counting warps contribute zeros).
    c0 = __reduce_add_sync(0xffffffffu, c0);
    c1 = __reduce_add_sync(0xffffffffu, c1);
    c2 = __reduce_add_sync(0xffffffffu, c2);
    c3 = __reduce_add_sync(0xffffffffu, c3);
    __syncthreads();
    if (l32 == 0) {
        atomicAdd(&scnt[0], (unsigned)c0);
        atomicAdd(&scnt[1], (unsigned)c1);
        atomicAdd(&scnt[2], (unsigned)c2);
        atomicAdd(&scnt[3], (unsigned)c3);
    }
    __syncthreads();

    {
        const float* sf = (const float*)s;
        const int c = tid >> 6;
        const int b = (tid & 63) * 4;
        #pragma unroll
        for (int j = 0; j < 4; j++) {
            float v = sf[(c * 4 + 0) * D + b + j] + sf[(c * 4 + 1) * D + b + j]
                    + sf[(c * 4 + 2) * D + b + j] + sf[(c * 4 + 3) * D + b + j];
            atomicAdd(&g_sum[c * D + b + j], v);
        }
    }
    if (tid < NC) atomicAdd(&g_cnt[tid], scnt[tid]);

    // ---- Last block: fused finalize ----
    __shared__ unsigned int s_last;
    __threadfence();
    if (tid == 0)
        s_last = (atomicAdd(&g_done, 1u) == (unsigned)(gridDim.x - 1));
    __syncthreads();
    if (!s_last) return;
    __threadfence();   // acquire: see all blocks' atomics

    const int c = tid >> 6;
    const int b = (tid & 63) * 4;

    const float inv_cnt = 1.0f / (float)g_cnt[c];
    float mx = g_sum[c * D + b + 0] * inv_cnt;
    float my = g_sum[c * D + b + 1] * inv_cnt;
    float mz = g_sum[c * D + b + 2] * inv_cnt;
    float mw = g_sum[c * D + b + 3] * inv_cnt;

    __shared__ float red[256];
    red[tid] = mx * mx + my * my + mz * mz + mw * mw;
    __syncthreads();
    #pragma unroll
    for (int st = 32; st >= 1; st >>= 1) {
        if ((tid & 63) < st) red[tid] += red[tid + st];
        __syncthreads();
    }

    const float inv = 1.0f / fmaxf(sqrtf(red[c * 64]), 1e-12f);
    out[c * D + b + 0] = mx * inv;
    out[c * D + b + 1] = my * inv;
    out[c * D + b + 2] = mz * inv;
    out[c * D + b + 3] = mw * inv;

    const int tail = out_size - NC * D;
    if (tail > 0 && tid < tail && tid < NC)
        out[NC * D + tid] = (float)tid;

    // ---- Self-clean scratch for the next graph replay ----
    __syncthreads();   // everyone done reading g_sum/g_cnt
    g_sum[c * D + b + 0] = 0.0f;
    g_sum[c * D + b + 1] = 0.0f;
    g_sum[c * D + b + 2] = 0.0f;
    g_sum[c * D + b + 3] = 0.0f;
    if (tid < NC) g_cnt[tid] = 0u;
    if (tid == 0) g_done = 0u;
}

extern "C" void kernel_launch(void* const* d_in, const int* in_sizes, int n_in,
                              void* d_out, int out_size)
{
    const ulonglong2* feat   = (const ulonglong2*)d_in[0];
    const int*        labels = (const int*)d_in[1];
    float*            out    = (float*)d_out;

    const int nrows = in_sizes[1];     // 1,000,000

    int numSM = 0, blocksPerSM = 0;
    int grid = 608;
    if (cudaDeviceGetAttribute(&numSM, cudaDevAttrMultiProcessorCount, 0) == cudaSuccess &&
        cudaOccupancyMaxActiveBlocksPerMultiprocessor(&blocksPerSM, accum_kernel, 256, 0) == cudaSuccess &&
        numSM > 0 && blocksPerSM > 0) {
        grid = numSM * blocksPerSM;
    }
    const int nunits = (nrows + 31) >> 5;
    const int maxGrid = (nunits + 3) / 4;
    if (grid > maxGrid) grid = maxGrid;

    accum_kernel<<<grid, 256>>>(feat, labels, nrows, out, out_size);
}

// round 9
// speedup vs baseline: 1.0481x; 1.0481x over previous
#include <cuda_runtime.h>
#include <cuda_bf16.h>

#define NC 4
#define D  256

__device__ float        g_sum[NC * D];   // zero at load; self-cleaned each run
__device__ unsigned int g_cnt[NC];
__device__ unsigned int g_done;

// Two packed 1.0f floats for the f32x2 mask.
#define ONE2 0x3F8000003F800000ULL
// Packed dual-FMA (Blackwell f32x2): acc += v * m (2 lanes at once)
#define FMA2(acc, v, m) \
    asm("fma.rn.f32x2 %0, %1, %2, %0;" : "+l"(acc) : "l"(v), "l"(m))

#define ACC_ROW(v, lbl)                                                   \
    do {                                                                  \
        const unsigned long long _m0 = ((lbl) == 0) ? ONE2 : 0ULL;        \
        const unsigned long long _m1 = ((lbl) == 1) ? ONE2 : 0ULL;        \
        const unsigned long long _m2 = ((lbl) == 2) ? ONE2 : 0ULL;        \
        const unsigned long long _m3 = ((lbl) == 3) ? ONE2 : 0ULL;        \
        FMA2(a00, (v).x, _m0); FMA2(a01, (v).y, _m0);                     \
        FMA2(a10, (v).x, _m1); FMA2(a11, (v).y, _m1);                     \
        FMA2(a20, (v).x, _m2); FMA2(a21, (v).y, _m2);                     \
        FMA2(a30, (v).x, _m3); FMA2(a31, (v).y, _m3);                     \
    } while (0)

// Per-group named barrier (64 threads = 2 warps), ids 1..4.
#define GROUP_BAR(g) \
    asm volatile("bar.sync %0, 64;" :: "r"((g) + 1) : "memory")

// 256 threads/CTA = 4 independent groups of 64. Unit = 32 contiguous rows per
// group. Labels double-buffered in per-group smem slabs; warp0 prefetches the
// NEXT unit's labels while the group consumes the current one. Only per-group
// named barriers -> groups drift out of phase, SM load stream never drains.
__global__ __launch_bounds__(256, 4) void accum_kernel(
    const ulonglong2* __restrict__ feat,   // [nrows*64] 16B chunks
    const int*        __restrict__ labels, // [nrows]
    int nrows,
    float* __restrict__ out, int out_size)
{
    const int tid  = threadIdx.x;
    const int grp  = tid >> 6;
    const int lane = tid & 63;   // float4 column within the row
    const int l32  = tid & 31;
    const bool w0  = (tid & 32) == 0;   // warp0 of the group

    __shared__ int slab[4][2][32];

    unsigned long long a00 = 0, a01 = 0, a10 = 0, a11 = 0;
    unsigned long long a20 = 0, a21 = 0, a30 = 0, a31 = 0;
    int c0 = 0, c1 = 0, c2 = 0, c3 = 0;

    const int nunits  = (nrows + 31) >> 5;
    const int ustride = gridDim.x * 4;
    int u = blockIdx.x * 4 + grp;
    int p = 0;

    // Preload labels for the first unit.
    if (u < nunits && w0) {
        const int idx = (u << 5) + l32;
        const int lbl = (idx < nrows) ? labels[idx] : -1;
        slab[grp][0][l32] = lbl;
        c0 += (lbl == 0); c1 += (lbl == 1);
        c2 += (lbl == 2); c3 += (lbl == 3);
    }
    GROUP_BAR(grp);

    for (; u < nunits; u += ustride) {
        // Prefetch next unit's labels into the alternate slab (+ count).
        const int nextu = u + ustride;
        if (w0 && nextu < nunits) {
            const int idx = (nextu << 5) + l32;
            const int lbl = (idx < nrows) ? labels[idx] : -1;
            slab[grp][p ^ 1][l32] = lbl;
            c0 += (lbl == 0); c1 += (lbl == 1);
            c2 += (lbl == 2); c3 += (lbl == 3);
        }

        // Consume current unit: 32 rows, batches of 8 front-batched LDG.128.
        const int rbase = u << 5;
        const size_t fbase = (size_t)rbase * 64 + lane;
        const int* myl = slab[grp][p];
        const int lim = nrows - rbase;

        if (lim >= 32) {
            #pragma unroll
            for (int j0 = 0; j0 < 32; j0 += 8) {
                ulonglong2 v[8];
                #pragma unroll
                for (int k = 0; k < 8; k++)
                    v[k] = feat[fbase + (size_t)(j0 + k) * 64];
                #pragma unroll
                for (int k = 0; k < 8; k++)
                    ACC_ROW(v[k], myl[j0 + k]);
            }
        } else {
            for (int j = 0; j < lim; j++) {
                const ulonglong2 v = feat[fbase + (size_t)j * 64];
                ACC_ROW(v, myl[j]);
            }
        }

        GROUP_BAR(grp);   // readers done with p; prefetch of p^1 visible
        p ^= 1;
    }

    // ---- Block reduction into global scratch ----
    __shared__ unsigned long long s[NC][4][128];   // float[NC][4][256] view
    __shared__ unsigned int scnt[NC];

    if (tid < NC) scnt[tid] = 0u;

    const int pp = lane * 2;
    s[0][grp][pp] = a00; s[0][grp][pp + 1] = a01;
    s[1][grp][pp] = a10; s[1][grp][pp + 1] = a11;
    s[2][grp][pp] = a20; s[2][grp][pp + 1] = a21;
    s[3][grp][pp] = a30; s[3][grp][pp + 1] = a31;

    // Warp-level count reduce (warp1 of each group holds zeros).
    c0 = __reduce_add_sync(0xffffffffu, c0);
    c1 = __reduce_add_sync(0xffffffffu, c1);
    c2 = __reduce_add_sync(0xffffffffu, c2);
    c3 = __reduce_add_sync(0xffffffffu, c3);
    __syncthreads();
    if (l32 == 0 && w0) {
        atomicAdd(&scnt[0], (unsigned)c0);
        atomicAdd(&scnt[1], (unsigned)c1);
        atomicAdd(&scnt[2], (unsigned)c2);
        atomicAdd(&scnt[3], (unsigned)c3);
    }
    __syncthreads();

    {
        const float* sf = (const float*)s;
        const int c = tid >> 6;
        const int b = (tid & 63) * 4;
        #pragma unroll
        for (int j = 0; j < 4; j++) {
            float v = sf[(c * 4 + 0) * D + b + j] + sf[(c * 4 + 1) * D + b + j]
                    + sf[(c * 4 + 2) * D + b + j] + sf[(c * 4 + 3) * D + b + j];
            atomicAdd(&g_sum[c * D + b + j], v);
        }
    }
    if (tid < NC) atomicAdd(&g_cnt[tid], scnt[tid]);

    // ---- Last block: fused finalize ----
    __shared__ unsigned int s_last;
    __threadfence();
    if (tid == 0)
        s_last = (atomicAdd(&g_done, 1u) == (unsigned)(gridDim.x - 1));
    __syncthreads();
    if (!s_last) return;
    __threadfence();   // acquire: see all blocks' atomics

    const int c = tid >> 6;
    const int b = (tid & 63) * 4;

    const float inv_cnt = 1.0f / (float)g_cnt[c];
    float mx = g_sum[c * D + b + 0] * inv_cnt;
    float my = g_sum[c * D + b + 1] * inv_cnt;
    float mz = g_sum[c * D + b + 2] * inv_cnt;
    float mw = g_sum[c * D + b + 3] * inv_cnt;

    __shared__ float red[256];
    red[tid] = mx * mx + my * my + mz * mz + mw * mw;
    __syncthreads();
    #pragma unroll
    for (int st = 32; st >= 1; st >>= 1) {
        if ((tid & 63) < st) red[tid] += red[tid + st];
        __syncthreads();
    }

    const float inv = 1.0f / fmaxf(sqrtf(red[c * 64]), 1e-12f);
    out[c * D + b + 0] = mx * inv;
    out[c * D + b + 1] = my * inv;
    out[c * D + b + 2] = mz * inv;
    out[c * D + b + 3] = mw * inv;

    const int tail = out_size - NC * D;
    if (tail > 0 && tid < tail && tid < NC)
        out[NC * D + tid] = (float)tid;

    // ---- Self-clean scratch for the next graph replay ----
    __syncthreads();
    g_sum[c * D + b + 0] = 0.0f;
    g_sum[c * D + b + 1] = 0.0f;
    g_sum[c * D + b + 2] = 0.0f;
    g_sum[c * D + b + 3] = 0.0f;
    if (tid < NC) g_cnt[tid] = 0u;
    if (tid == 0) g_done = 0u;
}

extern "C" void kernel_launch(void* const* d_in, const int* in_sizes, int n_in,
                              void* d_out, int out_size)
{
    const ulonglong2* feat   = (const ulonglong2*)d_in[0];
    const int*        labels = (const int*)d_in[1];
    float*            out    = (float*)d_out;

    const int nrows = in_sizes[1];     // 1,000,000

    int numSM = 0, blocksPerSM = 0;
    int grid = 608;
    if (cudaDeviceGetAttribute(&numSM, cudaDevAttrMultiProcessorCount, 0) == cudaSuccess &&
        cudaOccupancyMaxActiveBlocksPerMultiprocessor(&blocksPerSM, accum_kernel, 256, 0) == cudaSuccess &&
        numSM > 0 && blocksPerSM > 0) {
        grid = numSM * blocksPerSM;
    }
    const int nunits = (nrows + 31) >> 5;
    const int maxGrid = (nunits + 3) / 4;
    if (grid > maxGrid) grid = maxGrid;

    accum_kernel<<<grid, 256>>>(feat, labels, nrows, out, out_size);
}

// round 10
// speedup vs baseline: 1.0605x; 1.0118x over previous
#include <cuda_runtime.h>
#include <cuda_bf16.h>

#define NC 4
#define D  256
#define CHUNK 512          // rows per ticket; 128 per 64-thread group

__device__ float        g_sum[NC * D];   // zero at load; self-cleaned each run
__device__ unsigned int g_cnt[NC];
__device__ unsigned int g_done;
__device__ unsigned int g_ticket;

// Two packed 1.0f floats for the f32x2 mask.
#define ONE2 0x3F8000003F800000ULL
// Packed dual-FMA (Blackwell f32x2): acc += v * m (2 lanes at once)
#define FMA2(acc, v, m) \
    asm("fma.rn.f32x2 %0, %1, %2, %0;" : "+l"(acc) : "l"(v), "l"(m))

#define ACC_ROW(v, lbl)                                                   \
    do {                                                                  \
        const unsigned long long _m0 = ((lbl) == 0) ? ONE2 : 0ULL;        \
        const unsigned long long _m1 = ((lbl) == 1) ? ONE2 : 0ULL;        \
        const unsigned long long _m2 = ((lbl) == 2) ? ONE2 : 0ULL;        \
        const unsigned long long _m3 = ((lbl) == 3) ? ONE2 : 0ULL;        \
        FMA2(a00, (v).x, _m0); FMA2(a01, (v).y, _m0);                     \
        FMA2(a10, (v).x, _m1); FMA2(a11, (v).y, _m1);                     \
        FMA2(a20, (v).x, _m2); FMA2(a21, (v).y, _m2);                     \
        FMA2(a30, (v).x, _m3); FMA2(a31, (v).y, _m3);                     \
    } while (0)

// 256 threads/CTA = 4 groups of 64. Dynamic ticket -> chunk of 512 rows.
// Phase A: stage 512 labels coalesced (counts free). Phase B: each group
// streams its 128 rows (compiler-batched unroll 8). 2 barriers + 1 ticket
// per 512 rows -> overhead/byte is 4x lower than the 174.6us baseline.
__global__ __launch_bounds__(256) void accum_kernel(
    const ulonglong2* __restrict__ feat,   // [nrows*64] 16B chunks
    const int*        __restrict__ labels, // [nrows]
    int nrows,
    float* __restrict__ out, int out_size)
{
    const int tid  = threadIdx.x;
    const int grp  = tid >> 6;
    const int lane = tid & 63;   // float4 column within the row
    const int l32  = tid & 31;

    __shared__ int slab[CHUNK];
    __shared__ int s_t;

    unsigned long long a00 = 0, a01 = 0, a10 = 0, a11 = 0;
    unsigned long long a20 = 0, a21 = 0, a30 = 0, a31 = 0;
    int c0 = 0, c1 = 0, c2 = 0, c3 = 0;

    const int nchunks = (nrows + CHUNK - 1) / CHUNK;

    for (;;) {
        if (tid == 0) s_t = (int)atomicAdd(&g_ticket, 1u);
        __syncthreads();                    // ticket visible; consume of prev chunk done
        const int ch = s_t;
        if (ch >= nchunks) break;

        const int rbase = ch * CHUNK;

        // Phase A: stage 512 labels (two coalesced 1KB loads), count for free.
        {
            const int i0 = rbase + tid;
            const int i1 = i0 + 256;
            const int lb0 = (i0 < nrows) ? labels[i0] : -1;
            const int lb1 = (i1 < nrows) ? labels[i1] : -1;
            slab[tid]       = lb0;
            slab[tid + 256] = lb1;
            c0 += (lb0 == 0) + (lb1 == 0);
            c1 += (lb0 == 1) + (lb1 == 1);
            c2 += (lb0 == 2) + (lb1 == 2);
            c3 += (lb0 == 3) + (lb1 == 3);
        }
        __syncthreads();                    // labels visible

        // Phase B: this group's 128 rows.
        const int rowbase = rbase + grp * 128;
        const size_t fbase = (size_t)rowbase * 64 + lane;
        const int* myl = &slab[grp * 128];

        int lim = nrows - rowbase;
        if (lim > 128) lim = 128;

        if (lim == 128) {
            #pragma unroll 8
            for (int j = 0; j < 128; j++) {
                const int lbl = myl[j];
                const ulonglong2 v = feat[fbase + (size_t)j * 64];
                ACC_ROW(v, lbl);
            }
        } else {
            for (int j = 0; j < lim; j++) {
                const int lbl = myl[j];
                const ulonglong2 v = feat[fbase + (size_t)j * 64];
                ACC_ROW(v, lbl);
            }
        }
        // next iteration's first __syncthreads protects slab reuse
    }

    // ---- Block reduction into global scratch ----
    __shared__ unsigned long long s[NC][4][128];   // float[NC][4][256] view
    __shared__ unsigned int scnt[NC];

    if (tid < NC) scnt[tid] = 0u;

    const int pp = lane * 2;
    s[0][grp][pp] = a00; s[0][grp][pp + 1] = a01;
    s[1][grp][pp] = a10; s[1][grp][pp + 1] = a11;
    s[2][grp][pp] = a20; s[2][grp][pp + 1] = a21;
    s[3][grp][pp] = a30; s[3][grp][pp + 1] = a31;

    c0 = __reduce_add_sync(0xffffffffu, c0);
    c1 = __reduce_add_sync(0xffffffffu, c1);
    c2 = __reduce_add_sync(0xffffffffu, c2);
    c3 = __reduce_add_sync(0xffffffffu, c3);
    __syncthreads();
    if (l32 == 0) {
        atomicAdd(&scnt[0], (unsigned)c0);
        atomicAdd(&scnt[1], (unsigned)c1);
        atomicAdd(&scnt[2], (unsigned)c2);
        atomicAdd(&scnt[3], (unsigned)c3);
    }
    __syncthreads();

    {
        const float* sf = (const float*)s;
        const int c = tid >> 6;
        const int b = (tid & 63) * 4;
        #pragma unroll
        for (int j = 0; j < 4; j++) {
            float v = sf[(c * 4 + 0) * D + b + j] + sf[(c * 4 + 1) * D + b + j]
                    + sf[(c * 4 + 2) * D + b + j] + sf[(c * 4 + 3) * D + b + j];
            atomicAdd(&g_sum[c * D + b + j], v);
        }
    }
    if (tid < NC) atomicAdd(&g_cnt[tid], scnt[tid]);

    // ---- Last block: fused finalize ----
    __shared__ unsigned int s_last;
    __threadfence();
    if (tid == 0)
        s_last = (atomicAdd(&g_done, 1u) == (unsigned)(gridDim.x - 1));
    __syncthreads();
    if (!s_last) return;
    __threadfence();   // acquire: see all blocks' atomics

    const int c = tid >> 6;
    const int b = (tid & 63) * 4;

    const float inv_cnt = 1.0f / (float)g_cnt[c];
    float mx = g_sum[c * D + b + 0] * inv_cnt;
    float my = g_sum[c * D + b + 1] * inv_cnt;
    float mz = g_sum[c * D + b + 2] * inv_cnt;
    float mw = g_sum[c * D + b + 3] * inv_cnt;

    __shared__ float red[256];
    red[tid] = mx * mx + my * my + mz * mz + mw * mw;
    __syncthreads();
    #pragma unroll
    for (int st = 32; st >= 1; st >>= 1) {
        if ((tid & 63) < st) red[tid] += red[tid + st];
        __syncthreads();
    }

    const float inv = 1.0f / fmaxf(sqrtf(red[c * 64]), 1e-12f);
    out[c * D + b + 0] = mx * inv;
    out[c * D + b + 1] = my * inv;
    out[c * D + b + 2] = mz * inv;
    out[c * D + b + 3] = mw * inv;

    const int tail = out_size - NC * D;
    if (tail > 0 && tid < tail && tid < NC)
        out[NC * D + tid] = (float)tid;

    // ---- Self-clean scratch for the next graph replay ----
    __syncthreads();
    g_sum[c * D + b + 0] = 0.0f;
    g_sum[c * D + b + 1] = 0.0f;
    g_sum[c * D + b + 2] = 0.0f;
    g_sum[c * D + b + 3] = 0.0f;
    if (tid < NC) g_cnt[tid] = 0u;
    if (tid == 0) { g_done = 0u; g_ticket = 0u; }
}

extern "C" void kernel_launch(void* const* d_in, const int* in_sizes, int n_in,
                              void* d_out, int out_size)
{
    const ulonglong2* feat   = (const ulonglong2*)d_in[0];
    const int*        labels = (const int*)d_in[1];
    float*            out    = (float*)d_out;

    const int nrows = in_sizes[1];     // 1,000,000

    int numSM = 0, blocksPerSM = 0;
    int grid = 608;
    if (cudaDeviceGetAttribute(&numSM, cudaDevAttrMultiProcessorCount, 0) == cudaSuccess &&
        cudaOccupancyMaxActiveBlocksPerMultiprocessor(&blocksPerSM, accum_kernel, 256, 0) == cudaSuccess &&
        numSM > 0 && blocksPerSM > 0) {
        grid = numSM * blocksPerSM;
    }
    const int nchunks = (nrows + CHUNK - 1) / CHUNK;
    if (grid > nchunks) grid = nchunks;

    accum_kernel<<<grid, 256>>>(feat, labels, nrows, out, out_size);
}

// round 12
// speedup vs baseline: 1.0688x; 1.0079x over previous
#include <cuda_runtime.h>
#include <cuda_bf16.h>

#define NC 4
#define D  256
#define CHUNK 128          // rows per ticket; 32 per 64-thread group

__device__ float        g_sum[NC * D];   // zero at load; self-cleaned each run
__device__ unsigned int g_cnt[NC];
__device__ unsigned int g_done;
__device__ unsigned int g_ticket;

// Two packed 1.0f floats for the f32x2 mask.
#define ONE2 0x3F8000003F800000ULL
// Packed dual-FMA (Blackwell f32x2): acc += v * m (2 lanes at once)
#define FMA2(acc, v, m) \
    asm("fma.rn.f32x2 %0, %1, %2, %0;" : "+l"(acc) : "l"(v), "l"(m))

#define ACC_ROW(v, lbl)                                                   \
    do {                                                                  \
        const unsigned long long _m0 = ((lbl) == 0) ? ONE2 : 0ULL;        \
        const unsigned long long _m1 = ((lbl) == 1) ? ONE2 : 0ULL;        \
        const unsigned long long _m2 = ((lbl) == 2) ? ONE2 : 0ULL;        \
        const unsigned long long _m3 = ((lbl) == 3) ? ONE2 : 0ULL;        \
        FMA2(a00, (v).x, _m0); FMA2(a01, (v).y, _m0);                     \
        FMA2(a10, (v).x, _m1); FMA2(a11, (v).y, _m1);                     \
        FMA2(a20, (v).x, _m2); FMA2(a21, (v).y, _m2);                     \
        FMA2(a30, (v).x, _m3); FMA2(a31, (v).y, _m3);                     \
    } while (0)

// 256 threads/CTA = 4 groups of 64. Dynamic 128-row tickets. The next ticket
// and the next chunk's labels are prefetched DURING the current chunk's
// streaming phase, so the only per-chunk cost is one __syncthreads().
__global__ __launch_bounds__(256) void accum_kernel(
    const ulonglong2* __restrict__ feat,   // [nrows*64] 16B chunks
    const int*        __restrict__ labels, // [nrows]
    int nrows,
    float* __restrict__ out, int out_size)
{
    const int tid  = threadIdx.x;
    const int grp  = tid >> 6;
    const int lane = tid & 63;   // float4 column within the row
    const int l32  = tid & 31;

    __shared__ int slab[2][CHUNK];
    __shared__ int s_t[2];

    unsigned long long a00 = 0, a01 = 0, a10 = 0, a11 = 0;
    unsigned long long a20 = 0, a21 = 0, a30 = 0, a31 = 0;
    int c0 = 0, c1 = 0, c2 = 0, c3 = 0;

    const int nchunks = (nrows + CHUNK - 1) / CHUNK;

    // ---- Prologue: first ticket + its labels, prefetch second ticket ----
    if (tid == 0) s_t[0] = (int)atomicAdd(&g_ticket, 1u);
    __syncthreads();
    int ch = s_t[0];
    int p = 0;      // slab slot holding current chunk's labels
    int q = 1;      // s_t slot holding the NEXT chunk's ticket

    if (tid < CHUNK) {
        int lbl = -1;
        if (ch < nchunks) {
            const int idx = ch * CHUNK + tid;
            lbl = (idx < nrows) ? labels[idx] : -1;
            c0 += (lbl == 0); c1 += (lbl == 1);
            c2 += (lbl == 2); c3 += (lbl == 3);
        }
        slab[0][tid] = lbl;
    }
    if (tid == 0) s_t[1] = (int)atomicAdd(&g_ticket, 1u);
    __syncthreads();

    while (ch < nchunks) {
        const int nch = s_t[q];

        // Prefetch next chunk's labels into a register (overlaps phase B).
        int nlbl = -1;
        if (tid < CHUNK && nch < nchunks) {
            const int idx = nch * CHUNK + tid;
            nlbl = (idx < nrows) ? labels[idx] : -1;
        }

        // ---- Phase B: stream this group's 32 rows (batch-8 LDG.128) ----
        const int rowbase = ch * CHUNK + grp * 32;
        const size_t fbase = (size_t)rowbase * 64 + lane;
        const int* myl = &slab[p][grp * 32];

        int lim = nrows - rowbase;
        if (lim > 32) lim = 32;

        if (lim == 32) {
            #pragma unroll 8
            for (int j = 0; j < 32; j++) {
                const int lbl = myl[j];
                const ulonglong2 v = feat[fbase + (size_t)j * 64];
                ACC_ROW(v, lbl);
            }
        } else {
            for (int j = 0; j < lim; j++) {
                const int lbl = myl[j];
                const ulonglong2 v = feat[fbase + (size_t)j * 64];
                ACC_ROW(v, lbl);
            }
        }

        // ---- Commit prefetched state; grab ticket-after-next ----
        if (tid < CHUNK) {
            slab[p ^ 1][tid] = nlbl;
            if (nch < nchunks) {
                c0 += (nlbl == 0); c1 += (nlbl == 1);
                c2 += (nlbl == 2); c3 += (nlbl == 3);
            }
        }
        if (tid == 0 && nch < nchunks)
            s_t[q ^ 1] = (int)atomicAdd(&g_ticket, 1u);
        __syncthreads();            // one barrier per chunk

        ch = nch; p ^= 1; q ^= 1;
    }

    // ---- Block reduction into global scratch ----
    __shared__ unsigned long long s[NC][4][128];   // float[NC][4][256] view
    __shared__ unsigned int scnt[NC];

    if (tid < NC) scnt[tid] = 0u;

    const int pp = lane * 2;
    s[0][grp][pp] = a00; s[0][grp][pp + 1] = a01;
    s[1][grp][pp] = a10; s[1][grp][pp + 1] = a11;
    s[2][grp][pp] = a20; s[2][grp][pp + 1] = a21;
    s[3][grp][pp] = a30; s[3][grp][pp + 1] = a31;

    c0 = __reduce_add_sync(0xffffffffu, c0);
    c1 = __reduce_add_sync(0xffffffffu, c1);
    c2 = __reduce_add_sync(0xffffffffu, c2);
    c3 = __reduce_add_sync(0xffffffffu, c3);
    __syncthreads();
    if (l32 == 0) {
        atomicAdd(&scnt[0], (unsigned)c0);
        atomicAdd(&scnt[1], (unsigned)c1);
        atomicAdd(&scnt[2], (unsigned)c2);
        atomicAdd(&scnt[3], (unsigned)c3);
    }
    __syncthreads();

    {
        const float* sf = (const float*)s;
        const int c = tid >> 6;
        const int b = (tid & 63) * 4;
        #pragma unroll
        for (int j = 0; j < 4; j++) {
            float v = sf[(c * 4 + 0) * D + b + j] + sf[(c * 4 + 1) * D + b + j]
                    + sf[(c * 4 + 2) * D + b + j] + sf[(c * 4 + 3) * D + b + j];
            atomicAdd(&g_sum[c * D + b + j], v);
        }
    }
    if (tid < NC) atomicAdd(&g_cnt[tid], scnt[tid]);

    // ---- Last block: fused finalize ----
    __shared__ unsigned int s_last;
    __threadfence();
    if (tid == 0)
        s_last = (atomicAdd(&g_done, 1u) == (unsigned)(gridDim.x - 1));
    __syncthreads();
    if (!s_last) return;
    __threadfence();   // acquire: see all blocks' atomics

    const int c = tid >> 6;
    const int b = (tid & 63) * 4;

    const float inv_cnt = 1.0f / (float)g_cnt[c];
    float mx = g_sum[c * D + b + 0] * inv_cnt;
    float my = g_sum[c * D + b + 1] * inv_cnt;
    float mz = g_sum[c * D + b + 2] * inv_cnt;
    float mw = g_sum[c * D + b + 3] * inv_cnt;

    __shared__ float red[256];
    red[tid] = mx * mx + my * my + mz * mz + mw * mw;
    __syncthreads();
    #pragma unroll
    for (int st = 32; st >= 1; st >>= 1) {
        if ((tid & 63) < st) red[tid] += red[tid + st];
        __syncthreads();
    }

    const float inv = 1.0f / fmaxf(sqrtf(red[c * 64]), 1e-12f);
    out[c * D + b + 0] = mx * inv;
    out[c * D + b + 1] = my * inv;
    out[c * D + b + 2] = mz * inv;
    out[c * D + b + 3] = mw * inv;

    const int tail = out_size - NC * D;
    if (tail > 0 && tid < tail && tid < NC)
        out[NC * D + tid] = (float)tid;

    // ---- Self-clean scratch for the next graph replay ----
    __syncthreads();
    g_sum[c * D + b + 0] = 0.0f;
    g_sum[c * D + b + 1] = 0.0f;
    g_sum[c * D + b + 2] = 0.0f;
    g_sum[c * D + b + 3] = 0.0f;
    if (tid < NC) g_cnt[tid] = 0u;
    if (tid == 0) { g_done = 0u; g_ticket = 0u; }
}

extern "C" void kernel_launch(void* const* d_in, const int* in_sizes, int n_in,
                              void* d_out, int out_size)
{
    const ulonglong2* feat   = (const ulonglong2*)d_in[0];
    const int*        labels = (const int*)d_in[1];
    float*            out    = (float*)d_out;

    const int nrows = in_sizes[1];     // 1,000,000

    int numSM = 0, blocksPerSM = 0;
    int grid = 608;
    if (cudaDeviceGetAttribute(&numSM, cudaDevAttrMultiProcessorCount, 0) == cudaSuccess &&
        cudaOccupancyMaxActiveBlocksPerMultiprocessor(&blocksPerSM, accum_kernel, 256, 0) == cudaSuccess &&
        numSM > 0 && blocksPerSM > 0) {
        grid = numSM * blocksPerSM;
    }
    const int nchunks = (nrows + CHUNK - 1) / CHUNK;
    if (grid > nchunks) grid = nchunks;

    accum_kernel<<<grid, 256>>>(feat, labels, nrows, out, out_size);
}

// round 13
// speedup vs baseline: 1.1198x; 1.0477x over previous
#include <cuda_runtime.h>
#include <cuda_bf16.h>

#define NC 4
#define D  256
#define CHUNK 128          // rows per ticket; 16 per warp (8 warps/CTA)

typedef unsigned long long ULL;

__device__ float        g_sum[NC * D];   // zero at load; self-cleaned each run
__device__ unsigned int g_cnt[NC];
__device__ unsigned int g_done;
__device__ unsigned int g_ticket;

#define ONE2 0x3F8000003F800000ULL
#define FMA2(acc, v, m) \
    asm("fma.rn.f32x2 %0, %1, %2, %0;" : "+l"(acc) : "l"(v), "l"(m))

// 256-bit global load (sm_100+): 8 f32 -> 4 packed f32x2 ULLs.
#define LDG256(p, r0, r1, r2, r3)                                          \
    asm("{\n\t.reg .b32 t0,t1,t2,t3,t4,t5,t6,t7;\n\t"                      \
        "ld.global.nc.v8.b32 {t0,t1,t2,t3,t4,t5,t6,t7}, [%4];\n\t"         \
        "mov.b64 %0, {t0,t1};\n\tmov.b64 %1, {t2,t3};\n\t"                 \
        "mov.b64 %2, {t4,t5};\n\tmov.b64 %3, {t6,t7};\n\t}"                \
        : "=l"(r0), "=l"(r1), "=l"(r2), "=l"(r3) : "l"(p))

// Masked accumulate of one row's 8 floats (4 f32x2) into 4 class accumulators.
#define ACC8(v0, v1, v2, v3, lbl)                                          \
    do {                                                                   \
        const ULL _m0 = ((lbl) == 0) ? ONE2 : 0ULL;                        \
        const ULL _m1 = ((lbl) == 1) ? ONE2 : 0ULL;                        \
        const ULL _m2 = ((lbl) == 2) ? ONE2 : 0ULL;                        \
        const ULL _m3 = ((lbl) == 3) ? ONE2 : 0ULL;                        \
        FMA2(A00, v0, _m0); FMA2(A01, v1, _m0); FMA2(A02, v2, _m0); FMA2(A03, v3, _m0); \
        FMA2(A10, v0, _m1); FMA2(A11, v1, _m1); FMA2(A12, v2, _m1); FMA2(A13, v3, _m1); \
        FMA2(A20, v0, _m2); FMA2(A21, v1, _m2); FMA2(A22, v2, _m2); FMA2(A23, v3, _m2); \
        FMA2(A30, v0, _m3); FMA2(A31, v1, _m3); FMA2(A32, v2, _m3); FMA2(A33, v3, _m3); \
    } while (0)

// 256 threads/CTA = 8 warps. Warp = row engine: 32 lanes x 32B = one 1KB row
// via a single LDG.256 per lane. Chunk = 128 rows by dynamic ticket; warp w
// handles rows {w, w+8, ..., w+120}. Tickets + labels pipelined as in R12.
__global__ __launch_bounds__(256) void accum_kernel(
    const ULL* __restrict__ feat,          // [nrows*128] 8B words
    const int* __restrict__ labels,        // [nrows]
    int nrows,
    float* __restrict__ out, int out_size)
{
    const int tid = threadIdx.x;
    const int wid = tid >> 5;    // 0..7
    const int l32 = tid & 31;    // lane: 32B sub-block of the row

    __shared__ int slab[2][CHUNK];
    __shared__ int s_t[2];

    ULL A00 = 0, A01 = 0, A02 = 0, A03 = 0;
    ULL A10 = 0, A11 = 0, A12 = 0, A13 = 0;
    ULL A20 = 0, A21 = 0, A22 = 0, A23 = 0;
    ULL A30 = 0, A31 = 0, A32 = 0, A33 = 0;
    int c0 = 0, c1 = 0, c2 = 0, c3 = 0;

    const int nchunks = (nrows + CHUNK - 1) / CHUNK;

    // ---- Prologue: first ticket + labels, prefetch second ticket ----
    if (tid == 0) s_t[0] = (int)atomicAdd(&g_ticket, 1u);
    __syncthreads();
    int ch = s_t[0];
    int p = 0, q = 1;

    if (tid < CHUNK) {
        int lbl = -1;
        if (ch < nchunks) {
            const int idx = ch * CHUNK + tid;
            lbl = (idx < nrows) ? labels[idx] : -1;
            c0 += (lbl == 0); c1 += (lbl == 1);
            c2 += (lbl == 2); c3 += (lbl == 3);
        }
        slab[0][tid] = lbl;
    }
    if (tid == 0) s_t[1] = (int)atomicAdd(&g_ticket, 1u);
    __syncthreads();

    while (ch < nchunks) {
        const int nch = s_t[q];

        // Prefetch next chunk's labels into a register (overlaps phase B).
        int nlbl = -1;
        if (tid < CHUNK && nch < nchunks) {
            const int idx = nch * CHUNK + tid;
            nlbl = (idx < nrows) ? labels[idx] : -1;
        }

        // ---- Phase B: this warp's 16 rows (LDG.256 per lane) ----
        const int rbase = ch * CHUNK;
        const int* myl = slab[p];
        const ULL* rp = feat + (size_t)(rbase + wid) * 128 + l32 * 4;
        int lim = nrows - rbase;
        if (lim > CHUNK) lim = CHUNK;

        if (lim == CHUNK) {
            #pragma unroll 2
            for (int j = 0; j < 16; j += 2) {
                ULL v0, v1, v2, v3, v4, v5, v6, v7;
                LDG256(rp + (size_t)j * 1024,        v0, v1, v2, v3);
                LDG256(rp + (size_t)j * 1024 + 1024, v4, v5, v6, v7);
                const int lb0 = myl[wid + 8 * j];
                const int lb1 = myl[wid + 8 * j + 8];
                ACC8(v0, v1, v2, v3, lb0);
                ACC8(v4, v5, v6, v7, lb1);
            }
        } else {
            for (int j = 0; wid + 8 * j < lim; j++) {
                ULL v0, v1, v2, v3;
                LDG256(rp + (size_t)j * 1024, v0, v1, v2, v3);
                const int lb = myl[wid + 8 * j];
                ACC8(v0, v1, v2, v3, lb);
            }
        }

        // ---- Commit prefetched labels; grab ticket-after-next ----
        if (tid < CHUNK) {
            slab[p ^ 1][tid] = nlbl;
            if (nch < nchunks) {
                c0 += (nlbl == 0); c1 += (nlbl == 1);
                c2 += (nlbl == 2); c3 += (nlbl == 3);
            }
        }
        if (tid == 0 && nch < nchunks)
            s_t[q ^ 1] = (int)atomicAdd(&g_ticket, 1u);
        __syncthreads();            // one barrier per chunk

        ch = nch; p ^= 1; q ^= 1;
    }

    // ---- Block reduction into global scratch ----
    // su viewed as float[NC][8][256]: class c, warp w, column.
    __shared__ ULL su[NC][8][128];          // 32 KB
    __shared__ unsigned int scnt[NC];

    if (tid < NC) scnt[tid] = 0u;

    {
        const int b = l32 * 4;
        su[0][wid][b+0] = A00; su[0][wid][b+1] = A01; su[0][wid][b+2] = A02; su[0][wid][b+3] = A03;
        su[1][wid][b+0] = A10; su[1][wid][b+1] = A11; su[1][wid][b+2] = A12; su[1][wid][b+3] = A13;
        su[2][wid][b+0] = A20; su[2][wid][b+1] = A21; su[2][wid][b+2] = A22; su[2][wid][b+3] = A23;
        su[3][wid][b+0] = A30; su[3][wid][b+1] = A31; su[3][wid][b+2] = A32; su[3][wid][b+3] = A33;
    }

    c0 = __reduce_add_sync(0xffffffffu, c0);
    c1 = __reduce_add_sync(0xffffffffu, c1);
    c2 = __reduce_add_sync(0xffffffffu, c2);
    c3 = __reduce_add_sync(0xffffffffu, c3);
    __syncthreads();
    if (l32 == 0) {
        atomicAdd(&scnt[0], (unsigned)c0);
        atomicAdd(&scnt[1], (unsigned)c1);
        atomicAdd(&scnt[2], (unsigned)c2);
        atomicAdd(&scnt[3], (unsigned)c3);
    }
    __syncthreads();

    {
        const float* sf = (const float*)su;
        const int c = tid >> 6;
        const int b = (tid & 63) * 4;
        #pragma unroll
        for (int j = 0; j < 4; j++) {
            float v = 0.0f;
            #pragma unroll
            for (int w = 0; w < 8; w++)
                v += sf[(c * 8 + w) * D + b + j];
            atomicAdd(&g_sum[c * D + b + j], v);
        }
    }
    if (tid < NC) atomicAdd(&g_cnt[tid], scnt[tid]);

    // ---- Last block: fused finalize ----
    __shared__ unsigned int s_last;
    __threadfence();
    if (tid == 0)
        s_last = (atomicAdd(&g_done, 1u) == (unsigned)(gridDim.x - 1));
    __syncthreads();
    if (!s_last) return;
    __threadfence();   // acquire: see all blocks' atomics

    const int c = tid >> 6;
    const int b = (tid & 63) * 4;

    const float inv_cnt = 1.0f / (float)g_cnt[c];
    float mx = g_sum[c * D + b + 0] * inv_cnt;
    float my = g_sum[c * D + b + 1] * inv_cnt;
    float mz = g_sum[c * D + b + 2] * inv_cnt;
    float mw = g_sum[c * D + b + 3] * inv_cnt;

    __shared__ float red[256];
    red[tid] = mx * mx + my * my + mz * mz + mw * mw;
    __syncthreads();
    #pragma unroll
    for (int st = 32; st >= 1; st >>= 1) {
        if ((tid & 63) < st) red[tid] += red[tid + st];
        __syncthreads();
    }

    const float inv = 1.0f / fmaxf(sqrtf(red[c * 64]), 1e-12f);
    out[c * D + b + 0] = mx * inv;
    out[c * D + b + 1] = my * inv;
    out[c * D + b + 2] = mz * inv;
    out[c * D + b + 3] = mw * inv;

    const int tail = out_size - NC * D;
    if (tail > 0 && tid < tail && tid < NC)
        out[NC * D + tid] = (float)tid;

    // ---- Self-clean scratch for the next graph replay ----
    __syncthreads();
    g_sum[c * D + b + 0] = 0.0f;
    g_sum[c * D + b + 1] = 0.0f;
    g_sum[c * D + b + 2] = 0.0f;
    g_sum[c * D + b + 3] = 0.0f;
    if (tid < NC) g_cnt[tid] = 0u;
    if (tid == 0) { g_done = 0u; g_ticket = 0u; }
}

extern "C" void kernel_launch(void* const* d_in, const int* in_sizes, int n_in,
                              void* d_out, int out_size)
{
    const ULL* feat   = (const ULL*)d_in[0];
    const int* labels = (const int*)d_in[1];
    float*     out    = (float*)d_out;

    const int nrows = in_sizes[1];     // 1,000,000

    int numSM = 0, blocksPerSM = 0;
    int grid = 456;
    if (cudaDeviceGetAttribute(&numSM, cudaDevAttrMultiProcessorCount, 0) == cudaSuccess &&
        cudaOccupancyMaxActiveBlocksPerMultiprocessor(&blocksPerSM, accum_kernel, 256, 0) == cudaSuccess &&
        numSM > 0 && blocksPerSM > 0) {
        grid = numSM * blocksPerSM;
    }
    const int nchunks = (nrows + CHUNK - 1) / CHUNK;
    if (grid > nchunks) grid = nchunks;

    accum_kernel<<<grid, 256>>>(feat, labels, nrows, out, out_size);
}

// round 14
// speedup vs baseline: 1.1231x; 1.0029x over previous
#include <cuda_runtime.h>
#include <cuda_bf16.h>

#define NC 4
#define D  256
#define CHUNK 64           // rows per ticket; 8 per warp (8 warps/CTA)

typedef unsigned long long ULL;

__device__ float        g_sum[NC * D];   // zero at load; self-cleaned each run
__device__ unsigned int g_cnt[NC];
__device__ unsigned int g_done;
__device__ unsigned int g_ticket;

#define ONE2 0x3F8000003F800000ULL
#define FMA2(acc, v, m) \
    asm("fma.rn.f32x2 %0, %1, %2, %0;" : "+l"(acc) : "l"(v), "l"(m))

// 256-bit global load (sm_100+): 8 f32 -> 4 packed f32x2 ULLs.
#define LDG256(p, r0, r1, r2, r3)                                          \
    asm("{\n\t.reg .b32 t0,t1,t2,t3,t4,t5,t6,t7;\n\t"                      \
        "ld.global.nc.v8.b32 {t0,t1,t2,t3,t4,t5,t6,t7}, [%4];\n\t"         \
        "mov.b64 %0, {t0,t1};\n\tmov.b64 %1, {t2,t3};\n\t"                 \
        "mov.b64 %2, {t4,t5};\n\tmov.b64 %3, {t6,t7};\n\t}"                \
        : "=l"(r0), "=l"(r1), "=l"(r2), "=l"(r3) : "l"(p))

// Masked accumulate of one row's 8 floats (4 f32x2) into 4 class accumulators.
#define ACC8(v0, v1, v2, v3, lbl)                                          \
    do {                                                                   \
        const ULL _m0 = ((lbl) == 0) ? ONE2 : 0ULL;                        \
        const ULL _m1 = ((lbl) == 1) ? ONE2 : 0ULL;                        \
        const ULL _m2 = ((lbl) == 2) ? ONE2 : 0ULL;                        \
        const ULL _m3 = ((lbl) == 3) ? ONE2 : 0ULL;                        \
        FMA2(A00, v0, _m0); FMA2(A01, v1, _m0); FMA2(A02, v2, _m0); FMA2(A03, v3, _m0); \
        FMA2(A10, v0, _m1); FMA2(A11, v1, _m1); FMA2(A12, v2, _m1); FMA2(A13, v3, _m1); \
        FMA2(A20, v0, _m2); FMA2(A21, v1, _m2); FMA2(A22, v2, _m2); FMA2(A23, v3, _m2); \
        FMA2(A30, v0, _m3); FMA2(A31, v1, _m3); FMA2(A32, v2, _m3); FMA2(A33, v3, _m3); \
    } while (0)

// 256 threads/CTA = 8 warps. Warp = row engine: 32 lanes x 32B = one 1KB row
// via a single LDG.256 per lane. Chunk = 64 rows by dynamic ticket; warp w
// handles rows {w, w+8, ..., w+56}. Tickets + labels fully pipelined.
__global__ __launch_bounds__(256) void accum_kernel(
    const ULL* __restrict__ feat,          // [nrows*128] 8B words
    const int* __restrict__ labels,        // [nrows]
    int nrows,
    float* __restrict__ out, int out_size)
{
    const int tid = threadIdx.x;
    const int wid = tid >> 5;    // 0..7
    const int l32 = tid & 31;    // lane: 32B sub-block of the row

    __shared__ int slab[2][CHUNK];
    __shared__ int s_t[2];

    ULL A00 = 0, A01 = 0, A02 = 0, A03 = 0;
    ULL A10 = 0, A11 = 0, A12 = 0, A13 = 0;
    ULL A20 = 0, A21 = 0, A22 = 0, A23 = 0;
    ULL A30 = 0, A31 = 0, A32 = 0, A33 = 0;
    int c0 = 0, c1 = 0, c2 = 0, c3 = 0;

    const int nchunks = (nrows + CHUNK - 1) / CHUNK;

    // ---- Prologue: first ticket + labels, prefetch second ticket ----
    if (tid == 0) s_t[0] = (int)atomicAdd(&g_ticket, 1u);
    __syncthreads();
    int ch = s_t[0];
    int p = 0, q = 1;

    if (tid < CHUNK) {
        int lbl = -1;
        if (ch < nchunks) {
            const int idx = ch * CHUNK + tid;
            lbl = (idx < nrows) ? labels[idx] : -1;
            c0 += (lbl == 0); c1 += (lbl == 1);
            c2 += (lbl == 2); c3 += (lbl == 3);
        }
        slab[0][tid] = lbl;
    }
    if (tid == 0) s_t[1] = (int)atomicAdd(&g_ticket, 1u);
    __syncthreads();

    while (ch < nchunks) {
        const int nch = s_t[q];

        // Prefetch next chunk's labels into a register (overlaps phase B).
        int nlbl = -1;
        if (tid < CHUNK && nch < nchunks) {
            const int idx = nch * CHUNK + tid;
            nlbl = (idx < nrows) ? labels[idx] : -1;
        }

        // ---- Phase B: this warp's 8 rows (LDG.256 per lane, batch 2) ----
        const int rbase = ch * CHUNK;
        const int* myl = slab[p];
        const ULL* rp = feat + (size_t)(rbase + wid) * 128 + l32 * 4;
        int lim = nrows - rbase;
        if (lim > CHUNK) lim = CHUNK;

        if (lim == CHUNK) {
            #pragma unroll 2
            for (int j = 0; j < 8; j += 2) {
                ULL v0, v1, v2, v3, v4, v5, v6, v7;
                LDG256(rp + (size_t)j * 1024,        v0, v1, v2, v3);
                LDG256(rp + (size_t)j * 1024 + 1024, v4, v5, v6, v7);
                const int lb0 = myl[wid + 8 * j];
                const int lb1 = myl[wid + 8 * j + 8];
                ACC8(v0, v1, v2, v3, lb0);
                ACC8(v4, v5, v6, v7, lb1);
            }
        } else {
            for (int j = 0; wid + 8 * j < lim; j++) {
                ULL v0, v1, v2, v3;
                LDG256(rp + (size_t)j * 1024, v0, v1, v2, v3);
                const int lb = myl[wid + 8 * j];
                ACC8(v0, v1, v2, v3, lb);
            }
        }

        // ---- Commit prefetched labels; grab ticket-after-next ----
        if (tid < CHUNK) {
            slab[p ^ 1][tid] = nlbl;
            if (nch < nchunks) {
                c0 += (nlbl == 0); c1 += (nlbl == 1);
                c2 += (nlbl == 2); c3 += (nlbl == 3);
            }
        }
        if (tid == 0 && nch < nchunks)
            s_t[q ^ 1] = (int)atomicAdd(&g_ticket, 1u);
        __syncthreads();            // one barrier per chunk

        ch = nch; p ^= 1; q ^= 1;
    }

    // ---- Block reduction into global scratch ----
    // su viewed as float[NC][8][256]: class c, warp w, column.
    __shared__ ULL su[NC][8][128];          // 32 KB
    __shared__ unsigned int scnt[NC];

    if (tid < NC) scnt[tid] = 0u;

    {
        const int b = l32 * 4;
        su[0][wid][b+0] = A00; su[0][wid][b+1] = A01; su[0][wid][b+2] = A02; su[0][wid][b+3] = A03;
        su[1][wid][b+0] = A10; su[1][wid][b+1] = A11; su[1][wid][b+2] = A12; su[1][wid][b+3] = A13;
        su[2][wid][b+0] = A20; su[2][wid][b+1] = A21; su[2][wid][b+2] = A22; su[2][wid][b+3] = A23;
        su[3][wid][b+0] = A30; su[3][wid][b+1] = A31; su[3][wid][b+2] = A32; su[3][wid][b+3] = A33;
    }

    c0 = __reduce_add_sync(0xffffffffu, c0);
    c1 = __reduce_add_sync(0xffffffffu, c1);
    c2 = __reduce_add_sync(0xffffffffu, c2);
    c3 = __reduce_add_sync(0xffffffffu, c3);
    __syncthreads();
    if (l32 == 0) {
        atomicAdd(&scnt[0], (unsigned)c0);
        atomicAdd(&scnt[1], (unsigned)c1);
        atomicAdd(&scnt[2], (unsigned)c2);
        atomicAdd(&scnt[3], (unsigned)c3);
    }
    __syncthreads();

    {
        const float* sf = (const float*)su;
        const int c = tid >> 6;
        const int b = (tid & 63) * 4;
        #pragma unroll
        for (int j = 0; j < 4; j++) {
            float v = 0.0f;
            #pragma unroll
            for (int w = 0; w < 8; w++)
                v += sf[(c * 8 + w) * D + b + j];
            atomicAdd(&g_sum[c * D + b + j], v);
        }
    }
    if (tid < NC) atomicAdd(&g_cnt[tid], scnt[tid]);

    // ---- Last block: fused finalize ----
    __shared__ unsigned int s_last;
    __threadfence();
    if (tid == 0)
        s_last = (atomicAdd(&g_done, 1u) == (unsigned)(gridDim.x - 1));
    __syncthreads();
    if (!s_last) return;
    __threadfence();   // acquire: see all blocks' atomics

    const int c = tid >> 6;
    const int b = (tid & 63) * 4;

    const float inv_cnt = 1.0f / (float)g_cnt[c];
    float mx = g_sum[c * D + b + 0] * inv_cnt;
    float my = g_sum[c * D + b + 1] * inv_cnt;
    float mz = g_sum[c * D + b + 2] * inv_cnt;
    float mw = g_sum[c * D + b + 3] * inv_cnt;

    __shared__ float red[256];
    red[tid] = mx * mx + my * my + mz * mz + mw * mw;
    __syncthreads();
    #pragma unroll
    for (int st = 32; st >= 1; st >>= 1) {
        if ((tid & 63) < st) red[tid] += red[tid + st];
        __syncthreads();
    }

    const float inv = 1.0f / fmaxf(sqrtf(red[c * 64]), 1e-12f);
    out[c * D + b + 0] = mx * inv;
    out[c * D + b + 1] = my * inv;
    out[c * D + b + 2] = mz * inv;
    out[c * D + b + 3] = mw * inv;

    const int tail = out_size - NC * D;
    if (tail > 0 && tid < tail && tid < NC)
        out[NC * D + tid] = (float)tid;

    // ---- Self-clean scratch for the next graph replay ----
    __syncthreads();
    g_sum[c * D + b + 0] = 0.0f;
    g_sum[c * D + b + 1] = 0.0f;
    g_sum[c * D + b + 2] = 0.0f;
    g_sum[c * D + b + 3] = 0.0f;
    if (tid < NC) g_cnt[tid] = 0u;
    if (tid == 0) { g_done = 0u; g_ticket = 0u; }
}

extern "C" void kernel_launch(void* const* d_in, const int* in_sizes, int n_in,
                              void* d_out, int out_size)
{
    const ULL* feat   = (const ULL*)d_in[0];
    const int* labels = (const int*)d_in[1];
    float*     out    = (float*)d_out;

    const int nrows = in_sizes[1];     // 1,000,000

    int numSM = 0, blocksPerSM = 0;
    int grid = 456;
    if (cudaDeviceGetAttribute(&numSM, cudaDevAttrMultiProcessorCount, 0) == cudaSuccess &&
        cudaOccupancyMaxActiveBlocksPerMultiprocessor(&blocksPerSM, accum_kernel, 256, 0) == cudaSuccess &&
        numSM > 0 && blocksPerSM > 0) {
        grid = numSM * blocksPerSM;
    }
    const int nchunks = (nrows + CHUNK - 1) / CHUNK;
    if (grid > nchunks) grid = nchunks;

    accum_kernel<<<grid, 256>>>(feat, labels, nrows, out, out_size);
}

// round 15
// speedup vs baseline: 1.1471x; 1.0214x over previous
#include <cuda_runtime.h>
#include <cuda_bf16.h>

#define NC 4
#define D  256
#define CHUNK 64           // rows per ticket; 8 per warp (8 warps/CTA)

typedef unsigned long long ULL;

__device__ float        g_sum[NC * D];   // zero at load; self-cleaned each run
__device__ unsigned int g_cnt[NC];
__device__ unsigned int g_done;
__device__ unsigned int g_ticket;

#define ONE2 0x3F8000003F800000ULL
#define FMA2(acc, v, m) \
    asm("fma.rn.f32x2 %0, %1, %2, %0;" : "+l"(acc) : "l"(v), "l"(m))

// 256-bit global load (sm_100+): 8 f32 -> 4 packed f32x2 ULLs.
#define LDG256(p, r0, r1, r2, r3)                                          \
    asm("{\n\t.reg .b32 t0,t1,t2,t3,t4,t5,t6,t7;\n\t"                      \
        "ld.global.nc.v8.b32 {t0,t1,t2,t3,t4,t5,t6,t7}, [%4];\n\t"         \
        "mov.b64 %0, {t0,t1};\n\tmov.b64 %1, {t2,t3};\n\t"                 \
        "mov.b64 %2, {t4,t5};\n\tmov.b64 %3, {t6,t7};\n\t}"                \
        : "=l"(r0), "=l"(r1), "=l"(r2), "=l"(r3) : "l"(p))

// Masked accumulate of one row's 8 floats (4 f32x2) into 4 class accumulators.
#define ACC8(v0, v1, v2, v3, lbl)                                          \
    do {                                                                   \
        const ULL _m0 = ((lbl) == 0) ? ONE2 : 0ULL;                        \
        const ULL _m1 = ((lbl) == 1) ? ONE2 : 0ULL;                        \
        const ULL _m2 = ((lbl) == 2) ? ONE2 : 0ULL;                        \
        const ULL _m3 = ((lbl) == 3) ? ONE2 : 0ULL;                        \
        FMA2(A00, v0, _m0); FMA2(A01, v1, _m0); FMA2(A02, v2, _m0); FMA2(A03, v3, _m0); \
        FMA2(A10, v0, _m1); FMA2(A11, v1, _m1); FMA2(A12, v2, _m1); FMA2(A13, v3, _m1); \
        FMA2(A20, v0, _m2); FMA2(A21, v1, _m2); FMA2(A22, v2, _m2); FMA2(A23, v3, _m2); \
        FMA2(A30, v0, _m3); FMA2(A31, v1, _m3); FMA2(A32, v2, _m3); FMA2(A33, v3, _m3); \
    } while (0)

// 256 threads/CTA = 8 warps. Warp = row engine: 32 lanes x 32B = one 1KB row
// via a single LDG.256 per lane. Chunk = 64 rows by dynamic ticket; warp w
// handles rows {w, w+8, ..., w+56}. Batch-4 loads: all 4 row-loads issue
// before the first ACC8 consumes -> 4KB in flight per warp.
__global__ __launch_bounds__(256) void accum_kernel(
    const ULL* __restrict__ feat,          // [nrows*128] 8B words
    const int* __restrict__ labels,        // [nrows]
    int nrows,
    float* __restrict__ out, int out_size)
{
    const int tid = threadIdx.x;
    const int wid = tid >> 5;    // 0..7
    const int l32 = tid & 31;    // lane: 32B sub-block of the row

    __shared__ int slab[2][CHUNK];
    __shared__ int s_t[2];

    ULL A00 = 0, A01 = 0, A02 = 0, A03 = 0;
    ULL A10 = 0, A11 = 0, A12 = 0, A13 = 0;
    ULL A20 = 0, A21 = 0, A22 = 0, A23 = 0;
    ULL A30 = 0, A31 = 0, A32 = 0, A33 = 0;
    int c0 = 0, c1 = 0, c2 = 0, c3 = 0;

    const int nchunks = (nrows + CHUNK - 1) / CHUNK;

    // ---- Prologue: first ticket + labels, prefetch second ticket ----
    if (tid == 0) s_t[0] = (int)atomicAdd(&g_ticket, 1u);
    __syncthreads();
    int ch = s_t[0];
    int p = 0, q = 1;

    if (tid < CHUNK) {
        int lbl = -1;
        if (ch < nchunks) {
            const int idx = ch * CHUNK + tid;
            lbl = (idx < nrows) ? labels[idx] : -1;
            c0 += (lbl == 0); c1 += (lbl == 1);
            c2 += (lbl == 2); c3 += (lbl == 3);
        }
        slab[0][tid] = lbl;
    }
    if (tid == 0) s_t[1] = (int)atomicAdd(&g_ticket, 1u);
    __syncthreads();

    while (ch < nchunks) {
        const int nch = s_t[q];

        // Prefetch next chunk's labels into a register (overlaps phase B).
        int nlbl = -1;
        if (tid < CHUNK && nch < nchunks) {
            const int idx = nch * CHUNK + tid;
            nlbl = (idx < nrows) ? labels[idx] : -1;
        }

        // ---- Phase B: this warp's 8 rows, batch-4 LDG.256 ----
        const int rbase = ch * CHUNK;
        const int* myl = slab[p];
        const ULL* rp = feat + (size_t)(rbase + wid) * 128 + l32 * 4;
        int lim = nrows - rbase;
        if (lim > CHUNK) lim = CHUNK;

        if (lim == CHUNK) {
            #pragma unroll
            for (int j = 0; j < 8; j += 4) {
                ULL v0, v1, v2, v3, v4, v5, v6, v7;
                ULL v8, v9, va, vb, vc, vd, ve, vf;
                LDG256(rp + (size_t)j * 1024,        v0, v1, v2, v3);
                LDG256(rp + (size_t)j * 1024 + 1024, v4, v5, v6, v7);
                LDG256(rp + (size_t)j * 1024 + 2048, v8, v9, va, vb);
                LDG256(rp + (size_t)j * 1024 + 3072, vc, vd, ve, vf);
                const int lb0 = myl[wid + 8 * j];
                const int lb1 = myl[wid + 8 * j + 8];
                const int lb2 = myl[wid + 8 * j + 16];
                const int lb3 = myl[wid + 8 * j + 24];
                ACC8(v0, v1, v2, v3, lb0);
                ACC8(v4, v5, v6, v7, lb1);
                ACC8(v8, v9, va, vb, lb2);
                ACC8(vc, vd, ve, vf, lb3);
            }
        } else {
            for (int j = 0; wid + 8 * j < lim; j++) {
                ULL v0, v1, v2, v3;
                LDG256(rp + (size_t)j * 1024, v0, v1, v2, v3);
                const int lb = myl[wid + 8 * j];
                ACC8(v0, v1, v2, v3, lb);
            }
        }

        // ---- Commit prefetched labels; grab ticket-after-next ----
        if (tid < CHUNK) {
            slab[p ^ 1][tid] = nlbl;
            if (nch < nchunks) {
                c0 += (nlbl == 0); c1 += (nlbl == 1);
                c2 += (nlbl == 2); c3 += (nlbl == 3);
            }
        }
        if (tid == 0 && nch < nchunks)
            s_t[q ^ 1] = (int)atomicAdd(&g_ticket, 1u);
        __syncthreads();            // one barrier per chunk

        ch = nch; p ^= 1; q ^= 1;
    }

    // ---- Block reduction into global scratch ----
    // su viewed as float[NC][8][256]: class c, warp w, column.
    __shared__ ULL su[NC][8][128];          // 32 KB
    __shared__ unsigned int scnt[NC];

    if (tid < NC) scnt[tid] = 0u;

    {
        const int b = l32 * 4;
        su[0][wid][b+0] = A00; su[0][wid][b+1] = A01; su[0][wid][b+2] = A02; su[0][wid][b+3] = A03;
        su[1][wid][b+0] = A10; su[1][wid][b+1] = A11; su[1][wid][b+2] = A12; su[1][wid][b+3] = A13;
        su[2][wid][b+0] = A20; su[2][wid][b+1] = A21; su[2][wid][b+2] = A22; su[2][wid][b+3] = A23;
        su[3][wid][b+0] = A30; su[3][wid][b+1] = A31; su[3][wid][b+2] = A32; su[3][wid][b+3] = A33;
    }

    c0 = __reduce_add_sync(0xffffffffu, c0);
    c1 = __reduce_add_sync(0xffffffffu, c1);
    c2 = __reduce_add_sync(0xffffffffu, c2);
    c3 = __reduce_add_sync(0xffffffffu, c3);
    __syncthreads();
    if (l32 == 0) {
        atomicAdd(&scnt[0], (unsigned)c0);
        atomicAdd(&scnt[1], (unsigned)c1);
        atomicAdd(&scnt[2], (unsigned)c2);
        atomicAdd(&scnt[3], (unsigned)c3);
    }
    __syncthreads();

    {
        const float* sf = (const float*)su;
        const int c = tid >> 6;
        const int b = (tid & 63) * 4;
        #pragma unroll
        for (int j = 0; j < 4; j++) {
            float v = 0.0f;
            #pragma unroll
            for (int w = 0; w < 8; w++)
                v += sf[(c * 8 + w) * D + b + j];
            atomicAdd(&g_sum[c * D + b + j], v);
        }
    }
    if (tid < NC) atomicAdd(&g_cnt[tid], scnt[tid]);

    // ---- Last block: fused finalize ----
    __shared__ unsigned int s_last;
    __threadfence();
    if (tid == 0)
        s_last = (atomicAdd(&g_done, 1u) == (unsigned)(gridDim.x - 1));
    __syncthreads();
    if (!s_last) return;
    __threadfence();   // acquire: see all blocks' atomics

    const int c = tid >> 6;
    const int b = (tid & 63) * 4;

    const float inv_cnt = 1.0f / (float)g_cnt[c];
    float mx = g_sum[c * D + b + 0] * inv_cnt;
    float my = g_sum[c * D + b + 1] * inv_cnt;
    float mz = g_sum[c * D + b + 2] * inv_cnt;
    float mw = g_sum[c * D + b + 3] * inv_cnt;

    __shared__ float red[256];
    red[tid] = mx * mx + my * my + mz * mz + mw * mw;
    __syncthreads();
    #pragma unroll
    for (int st = 32; st >= 1; st >>= 1) {
        if ((tid & 63) < st) red[tid] += red[tid + st];
        __syncthreads();
    }

    const float inv = 1.0f / fmaxf(sqrtf(red[c * 64]), 1e-12f);
    out[c * D + b + 0] = mx * inv;
    out[c * D + b + 1] = my * inv;
    out[c * D + b + 2] = mz * inv;
    out[c * D + b + 3] = mw * inv;

    const int tail = out_size - NC * D;
    if (tail > 0 && tid < tail && tid < NC)
        out[NC * D + tid] = (float)tid;

    // ---- Self-clean scratch for the next graph replay ----
    __syncthreads();
    g_sum[c * D + b + 0] = 0.0f;
    g_sum[c * D + b + 1] = 0.0f;
    g_sum[c * D + b + 2] = 0.0f;
    g_sum[c * D + b + 3] = 0.0f;
    if (tid < NC) g_cnt[tid] = 0u;
    if (tid == 0) { g_done = 0u; g_ticket = 0u; }
}

extern "C" void kernel_launch(void* const* d_in, const int* in_sizes, int n_in,
                              void* d_out, int out_size)
{
    const ULL* feat   = (const ULL*)d_in[0];
    const int* labels = (const int*)d_in[1];
    float*     out    = (float*)d_out;

    const int nrows = in_sizes[1];     // 1,000,000

    int numSM = 0, blocksPerSM = 0;
    int grid = 456;
    if (cudaDeviceGetAttribute(&numSM, cudaDevAttrMultiProcessorCount, 0) == cudaSuccess &&
        cudaOccupancyMaxActiveBlocksPerMultiprocessor(&blocksPerSM, accum_kernel, 256, 0) == cudaSuccess &&
        numSM > 0 && blocksPerSM > 0) {
        grid = numSM * blocksPerSM;
    }
    const int nchunks = (nrows + CHUNK - 1) / CHUNK;
    if (grid > nchunks) grid = nchunks;

    accum_kernel<<<grid, 256>>>(feat, labels, nrows, out, out_size);
}